// round 9
// baseline (speedup 1.0000x reference)
#include <cuda_runtime.h>
#include <cuda_fp16.h>
#include <cstdint>

#define TPB     768
#define GTH     512      // GEMM threads (16 warps)
#define NB      128
#define SEQLEN  8194
#define NL      2048
#define DD      128
#define NT      128
#define NTILES  16
#define WSTR    272      // bytes per row (136 fp16) for W and H tiles

// shared memory layout (bytes)
#define OFF_WHI   0        // 128*272 = 34816
#define OFF_H     34816    // 2 parities x 34816 (H fp16 single)
#define OFF_MSH   104448   // 3*32*33 f32 = 12672
#define OFF_SSEQ  117120   // 4*132 i32 = 2112
#define OFF_VASH  119232   // 128 f32
#define OFF_EPART 119744   // 2 x 8 x 132 f32 = 8448
#define OFF_ESH   128192   // 128 f32
#define OFF_WSH   128704   // 128 f32
#define OFF_CTXP  129216   // 8*128 f32 = 4096
#define OFF_SCAL  133312   // 32 f32
#define SMEM_BYTES 133440

// named barriers: 1+p = HREADY, 3+p = GDONE, 5+p = EREADY, 7 = builder-internal
#define BAR_ARRIVE(id) asm volatile("bar.arrive %0, %1;" :: "r"(id), "r"(TPB) : "memory")
#define BAR_SYNC(id)   asm volatile("bar.sync %0, %1;"   :: "r"(id), "r"(TPB) : "memory")
#define BBAR()         asm volatile("bar.sync 7, 256;" ::: "memory")

__device__ __forceinline__ uint32_t smem_u32(const void* p) {
    uint32_t a;
    asm("{ .reg .u64 t; cvta.to.shared.u64 t, %1; cvt.u32.u64 %0, t; }" : "=r"(a) : "l"(p));
    return a;
}
__device__ __forceinline__ void ldsm_x4(uint32_t* r, uint32_t a) {
    asm volatile("ldmatrix.sync.aligned.m8n8.x4.shared.b16 {%0,%1,%2,%3}, [%4];"
                 : "=r"(r[0]), "=r"(r[1]), "=r"(r[2]), "=r"(r[3]) : "r"(a));
}
__device__ __forceinline__ void ldsm_x2(uint32_t& r0, uint32_t& r1, uint32_t a) {
    asm volatile("ldmatrix.sync.aligned.m8n8.x2.shared.b16 {%0,%1}, [%2];"
                 : "=r"(r0), "=r"(r1) : "r"(a));
}
__device__ __forceinline__ void mma16816(float* c, const uint32_t* a, uint32_t b0, uint32_t b1) {
    asm volatile("mma.sync.aligned.m16n8k16.row.col.f32.f16.f16.f32 "
                 "{%0,%1,%2,%3}, {%4,%5,%6,%7}, {%8,%9}, {%0,%1,%2,%3};"
                 : "+f"(c[0]), "+f"(c[1]), "+f"(c[2]), "+f"(c[3])
                 : "r"(a[0]), "r"(a[1]), "r"(a[2]), "r"(a[3]), "r"(b0), "r"(b1));
}
// accurate tanh: sign(x)*(1 - 2/(e^{2|x|}+1)); __expf rel err ~1e-7
__device__ __forceinline__ float tanh_acc(float x) {
    float ax = fminf(fabsf(x), 15.0f);
    float t  = __expf(2.0f * ax);
    float r  = 1.0f - __fdividef(2.0f, t + 1.0f);
    return copysignf(r, x);
}

// softmax scalars for tile parity pp + online ctx update (builder threads)
__device__ __forceinline__ void builder_epilogue(
    int pp, int bt, int lane, int bw, char* smem, float* epart, float* esh,
    float* wsh, float* scal, float* ctxAcc)
{
    const float* ep = epart + pp * 1056;
    if (bt < 128) {
        float e = 0.0f;
        #pragma unroll
        for (int m = 0; m < 8; m++) e += ep[m * 132 + bt];
        esh[bt] = e;
        float mx = e;
        #pragma unroll
        for (int off = 16; off; off >>= 1)
            mx = fmaxf(mx, __shfl_xor_sync(0xffffffffu, mx, off));
        if (lane == 0) scal[8 + (bt >> 5)] = mx;
    }
    BBAR();
    if (bt == 0) {
        float mt = fmaxf(fmaxf(scal[8], scal[9]), fmaxf(scal[10], scal[11]));
        float m_new = fmaxf(scal[0], mt);
        scal[3] = __expf(scal[0] - m_new);   // alpha
        scal[2] = m_new;
        scal[0] = m_new;
    }
    BBAR();
    if (bt < 128) {
        float wv = __expf(esh[bt] - scal[2]);
        wsh[bt] = wv;
        #pragma unroll
        for (int off = 16; off; off >>= 1)
            wv += __shfl_xor_sync(0xffffffffu, wv, off);
        if (lane == 0) scal[16 + (bt >> 5)] = wv;
    }
    BBAR();
    if (bt == 0)
        scal[1] = scal[1] * scal[3] + (scal[16] + scal[17] + scal[18] + scal[19]);
    BBAR();
    // ctx: warp bw handles rows n = bw*16..+16; lane owns e-quad lane*4..+4
    const float alpha = scal[3];
    const char* hb = smem + OFF_H + pp * 34816;
    float t0 = 0.0f, t1 = 0.0f, t2 = 0.0f, t3 = 0.0f;
    #pragma unroll 4
    for (int i = 0; i < 16; i++) {
        int n = bw * 16 + i;
        float wv = wsh[n];
        uint2 hv = *(const uint2*)(hb + (uint32_t)n * WSTR + (uint32_t)lane * 8u);
        float2 f0 = __half22float2(*(__half2*)&hv.x);
        float2 f1 = __half22float2(*(__half2*)&hv.y);
        t0 += wv * f0.x; t1 += wv * f0.y; t2 += wv * f1.x; t3 += wv * f1.y;
    }
    ctxAcc[0] = ctxAcc[0] * alpha + t0;
    ctxAcc[1] = ctxAcc[1] * alpha + t1;
    ctxAcc[2] = ctxAcc[2] * alpha + t2;
    ctxAcc[3] = ctxAcc[3] * alpha + t3;
}

__global__ void __launch_bounds__(TPB, 1)
dingo_kernel(const int*   __restrict__ seq,
             const float* __restrict__ emb,
             const float* __restrict__ convw,
             const float* __restrict__ convb,
             const float* __restrict__ Wa,
             const float* __restrict__ va,
             float*       __restrict__ out)
{
    extern __shared__ char smem[];
    const uint32_t sb = smem_u32(smem);
    float* Msh   = (float*)(smem + OFF_MSH);   // [3][32][33], bias folded into k=0
    int*   sseq  = (int*)  (smem + OFF_SSEQ);
    float* vash  = (float*)(smem + OFF_VASH);
    float* epart = (float*)(smem + OFF_EPART);
    float* esh   = (float*)(smem + OFF_ESH);
    float* wsh   = (float*)(smem + OFF_WSH);
    float* ctxp  = (float*)(smem + OFF_CTXP);
    float* scal  = (float*)(smem + OFF_SCAL);

    const int b    = blockIdx.x;
    const int tid  = threadIdx.x;
    const int wid  = tid >> 5;
    const int lane = tid & 31;
    const int* seqb = seq + b * SEQLEN;

    // ---- setup (all 768): W fp16 row-major [dw][e]; conv-fold tables ----
    for (int i = tid; i < DD * DD; i += TPB) {
        int dw = i >> 7, e = i & 127;
        *(__half*)(smem + OFF_WHI + dw * WSTR + e * 2) = __float2half_rn(Wa[i]);
    }
    for (int i = tid; i < 3 * 32 * 26; i += TPB) {
        int k = i / 832, r = i - k * 832;
        int c = r / 26, tt = r - c * 26;
        float acc = (k == 0) ? convb[c] : 0.0f;
        #pragma unroll
        for (int q = 0; q < 5; q++)
            acc += emb[tt * 5 + q] * convw[(c * 5 + q) * 3 + k];
        Msh[(k * 32 + c) * 33 + tt] = acc;
    }
    if (tid < 128) vash[tid] = va[tid];
    if (tid == 0) { scal[0] = -3.4e38f; scal[1] = 0.0f; }
    __syncthreads();

    if (tid < GTH) {
        // ========= GEMM warps (0-15): m16 x n64, single fp16 term =========
        const int gm = wid & 7, gn = wid >> 3;
        const uint32_t aBase = (uint32_t)(16 * gm + (lane & 15)) * WSTR
                             + (uint32_t)((lane >> 4) & 1) * 16u;
        const uint32_t aHi0 = sb + OFF_WHI + aBase;
        const int ll = lane & 15;
        const uint32_t bBase = (uint32_t)(64 * gn + (ll & 7)) * WSTR
                             + (uint32_t)((ll >> 3) & 1) * 16u;
        const int g = lane >> 2, tc = lane & 3;
        const float v0 = vash[16 * gm + g], v1 = vash[16 * gm + 8 + g];

        for (int tile = 0; tile < NTILES; tile++) {
            const int p = tile & 1;
            BAR_SYNC(1 + p);                       // H(tile) ready
            const uint32_t bH = sb + OFF_H + (uint32_t)p * 34816u + bBase;

            float acc[8][4];
            #pragma unroll
            for (int j = 0; j < 8; j++)
                #pragma unroll
                for (int q = 0; q < 4; q++) acc[j][q] = 0.0f;

            #pragma unroll 1
            for (int kk = 0; kk < 8; kk++) {
                const uint32_t ko = (uint32_t)kk * 32u;
                uint32_t a0[4];
                ldsm_x4(a0, aHi0 + ko);
                #pragma unroll
                for (int jh = 0; jh < 2; jh++) {
                    uint32_t bh[4][2];
                    #pragma unroll
                    for (int j4 = 0; j4 < 4; j4++) {
                        const uint32_t bo = (uint32_t)(jh * 4 + j4) * (8u * WSTR) + ko;
                        ldsm_x2(bh[j4][0], bh[j4][1], bH + bo);
                    }
                    #pragma unroll
                    for (int j4 = 0; j4 < 4; j4++)
                        mma16816(acc[jh * 4 + j4], a0, bh[j4][0], bh[j4][1]);
                }
            }
            BAR_ARRIVE(3 + p);                     // done reading H(tile)

            // tanh + va weighting -> e partials for this warp's 16 dw rows
            float* ep = epart + p * 1056 + gm * 132;
            #pragma unroll
            for (int j = 0; j < 8; j++) {
                float p0 = v0 * tanh_acc(acc[j][0]) + v1 * tanh_acc(acc[j][2]);
                float p1 = v0 * tanh_acc(acc[j][1]) + v1 * tanh_acc(acc[j][3]);
                #pragma unroll
                for (int off = 4; off <= 16; off <<= 1) {
                    p0 += __shfl_xor_sync(0xffffffffu, p0, off);
                    p1 += __shfl_xor_sync(0xffffffffu, p1, off);
                }
                if (lane < 4) {
                    ep[64 * gn + 8 * j + 2 * tc]     = p0;
                    ep[64 * gn + 8 * j + 2 * tc + 1] = p1;
                }
            }
            __threadfence_block();
            BAR_ARRIVE(5 + p);                     // e partials ready
        }
    } else {
        // ================= builder warps (16-23) =================
        const int bt = tid - GTH;
        const int bw = bt >> 5;            // builder warp 0-7
        const int c  = lane;               // channel
        const float* M0 = Msh + c * 33;           // bias folded in
        const float* M1 = Msh + (32 + c) * 33;
        const float* M2 = Msh + (64 + c) * 33;
        float ctxAcc[4] = {0.0f, 0.0f, 0.0f, 0.0f};

        for (int tile = 0; tile < NTILES; tile++) {
            const int p = tile & 1;
            BBAR();                                // prior tile reads done
            if (tile >= 2) BAR_SYNC(3 + p);        // GEMM(tile-2) done with buf p
            for (int i = bt; i < 4 * 130; i += 256) {
                int s = i / 130, o = i - s * 130;
                sseq[s * 132 + o] = seqb[s * NL + tile * NT + o];
            }
            BBAR();
            // build H(tile) into buf p: fp16, [n][e] rows; warp bw owns 16 n
            {
                char* hb = smem + OFF_H + p * 34816;
                const int nb = bw * 16;
                int u0[4], u1[4];
                #pragma unroll
                for (int s = 0; s < 4; s++) {
                    u0[s] = sseq[s * 132 + nb];
                    u1[s] = sseq[s * 132 + nb + 1];
                }
                #pragma unroll 2
                for (int i = 0; i < 16; i++) {
                    const int n = nb + i;
                    float v[4];
                    #pragma unroll
                    for (int s = 0; s < 4; s++) {
                        int u2 = sseq[s * 132 + n + 2];
                        v[s] = fmaxf(M0[u0[s]] + M1[u1[s]] + M2[u2], 0.0f);
                        u0[s] = u1[s]; u1[s] = u2;
                    }
                    uint32_t pk0, pk1;
                    asm("cvt.rn.f16x2.f32 %0, %1, %2;" : "=r"(pk0) : "f"(v[1]), "f"(v[0]));
                    asm("cvt.rn.f16x2.f32 %0, %1, %2;" : "=r"(pk1) : "f"(v[3]), "f"(v[2]));
                    uint2 pk = make_uint2(pk0, pk1);
                    *(uint2*)(hb + (uint32_t)n * WSTR + (uint32_t)c * 8u) = pk;
                }
            }
            __threadfence_block();
            BAR_ARRIVE(1 + p);                     // H(tile) ready
            if (tile >= 1) {
                const int pp = (tile - 1) & 1;
                BAR_SYNC(5 + pp);                  // e partials(tile-1) ready
                builder_epilogue(pp, bt, lane, bw, smem, epart, esh, wsh, scal, ctxAcc);
            }
        }
        // tail: epilogue for tile 15 (parity 1)
        BAR_SYNC(5 + 1);
        builder_epilogue(1, bt, lane, bw, smem, epart, esh, wsh, scal, ctxAcc);
        #pragma unroll
        for (int j = 0; j < 4; j++)
            ctxp[bw * 128 + lane * 4 + j] = ctxAcc[j];
    }

    __syncthreads();
    if (tid < 128) {
        float invz = 1.0f / scal[1];
        float s = 0.0f;
        #pragma unroll
        for (int q = 0; q < 8; q++) s += ctxp[q * 128 + tid];
        out[b * DD + tid] = s * invz;
    }
}

extern "C" void kernel_launch(void* const* d_in, const int* in_sizes, int n_in,
                              void* d_out, int out_size)
{
    const int*   seq   = (const int*)  d_in[0];  // [128, 8194] int32
    const float* emb   = (const float*)d_in[1];  // [26, 5]
    const float* convw = (const float*)d_in[2];  // [32, 5, 3]
    const float* convb = (const float*)d_in[3];  // [32]
    const float* Wa    = (const float*)d_in[4];  // [128, 128]
    const float* va    = (const float*)d_in[5];  // [128]
    float*       out   = (float*)d_out;          // [128, 128]

    cudaFuncSetAttribute(dingo_kernel,
                         cudaFuncAttributeMaxDynamicSharedMemorySize, SMEM_BYTES);
    dingo_kernel<<<NB, TPB, SMEM_BYTES>>>(seq, emb, convw, convb, Wa, va, out);
}

// round 10
// speedup vs baseline: 1.3864x; 1.3864x over previous
#include <cuda_runtime.h>
#include <cuda_fp16.h>
#include <cstdint>

#define TPB     512
#define NB      128
#define SEQLEN  8194
#define NL      2048
#define DD      128
#define NT      128
#define NTILES  16
#define WSTR    272      // bytes per row (136 fp16) for W and H tiles

// shared memory layout (bytes)
#define OFF_WHI   0        // 128*272 = 34816
#define OFF_H     34816    // 2 parities x 34816 (H fp16 single)
#define OFF_MSH   104448   // 3*32*33 f32 = 12672
#define OFF_SSEQ  117120   // 4*132 i32 = 2112
#define OFF_VASH  119232   // 128 f32
#define OFF_EPART 119744   // 2 x 4 x 132 f32 = 4224
#define OFF_WSH   124480   // 128 f32
#define OFF_CTXP  124992   // 8*128 f32 = 4096
#define OFF_SCAL  129088   // 32 f32
#define SMEM_BYTES 129216

// named barriers: 1+p = HREADY(512), 3+p = GDONE(512), 5+p = EREADY(288), 7 = builder BBAR(256)
#define BAR_ARRIVE(id, cnt) asm volatile("bar.arrive %0, %1;" :: "r"(id), "r"(cnt) : "memory")
#define BAR_SYNC(id, cnt)   asm volatile("bar.sync %0, %1;"   :: "r"(id), "r"(cnt) : "memory")
#define BBAR()              asm volatile("bar.sync 7, 256;" ::: "memory")

__device__ __forceinline__ uint32_t smem_u32(const void* p) {
    uint32_t a;
    asm("{ .reg .u64 t; cvta.to.shared.u64 t, %1; cvt.u32.u64 %0, t; }" : "=r"(a) : "l"(p));
    return a;
}
__device__ __forceinline__ void ldsm_x4(uint32_t* r, uint32_t a) {
    asm volatile("ldmatrix.sync.aligned.m8n8.x4.shared.b16 {%0,%1,%2,%3}, [%4];"
                 : "=r"(r[0]), "=r"(r[1]), "=r"(r[2]), "=r"(r[3]) : "r"(a));
}
__device__ __forceinline__ void ldsm_x2(uint32_t& r0, uint32_t& r1, uint32_t a) {
    asm volatile("ldmatrix.sync.aligned.m8n8.x2.shared.b16 {%0,%1}, [%2];"
                 : "=r"(r0), "=r"(r1) : "r"(a));
}
__device__ __forceinline__ void mma16816(float* c, const uint32_t* a, uint32_t b0, uint32_t b1) {
    asm volatile("mma.sync.aligned.m16n8k16.row.col.f32.f16.f16.f32 "
                 "{%0,%1,%2,%3}, {%4,%5,%6,%7}, {%8,%9}, {%0,%1,%2,%3};"
                 : "+f"(c[0]), "+f"(c[1]), "+f"(c[2]), "+f"(c[3])
                 : "r"(a[0]), "r"(a[1]), "r"(a[2]), "r"(a[3]), "r"(b0), "r"(b1));
}
// paired tanh via MUFU.TANH on f16x2: returns {tanh(a), tanh(b)}
__device__ __forceinline__ float2 tanh2(float a, float b) {
    uint32_t d2, t2;
    asm("cvt.rn.f16x2.f32 %0, %1, %2;" : "=r"(d2) : "f"(b), "f"(a));  // lo=a, hi=b
    asm("tanh.approx.f16x2 %0, %1;" : "=r"(t2) : "r"(d2));
    __half2 h = *reinterpret_cast<__half2*>(&t2);
    return __half22float2(h);   // x = tanh(a), y = tanh(b)
}

__global__ void __launch_bounds__(TPB, 1)
dingo_kernel(const int*   __restrict__ seq,
             const float* __restrict__ emb,
             const float* __restrict__ convw,
             const float* __restrict__ convb,
             const float* __restrict__ Wa,
             const float* __restrict__ va,
             float*       __restrict__ out)
{
    extern __shared__ char smem[];
    const uint32_t sb = smem_u32(smem);
    float* Msh   = (float*)(smem + OFF_MSH);   // [3][32][33], bias folded into k=0
    int*   sseq  = (int*)  (smem + OFF_SSEQ);
    float* vash  = (float*)(smem + OFF_VASH);
    float* epart = (float*)(smem + OFF_EPART);
    float* wsh   = (float*)(smem + OFF_WSH);
    float* ctxp  = (float*)(smem + OFF_CTXP);
    float* scal  = (float*)(smem + OFF_SCAL);

    const int b    = blockIdx.x;
    const int tid  = threadIdx.x;
    const int wid  = tid >> 5;
    const int lane = tid & 31;
    const int* seqb = seq + b * SEQLEN;

    // ---- setup (all 512): W fp16 row-major [dw][e]; conv-fold tables ----
    for (int i = tid; i < DD * DD; i += TPB) {
        int dw = i >> 7, e = i & 127;
        *(__half*)(smem + OFF_WHI + dw * WSTR + e * 2) = __float2half_rn(Wa[i]);
    }
    for (int i = tid; i < 3 * 32 * 26; i += TPB) {
        int k = i / 832, r = i - k * 832;
        int c = r / 26, tt = r - c * 26;
        float acc = (k == 0) ? convb[c] : 0.0f;
        #pragma unroll
        for (int q = 0; q < 5; q++)
            acc += emb[tt * 5 + q] * convw[(c * 5 + q) * 3 + k];
        Msh[(k * 32 + c) * 33 + tt] = acc;
    }
    if (tid < 128) vash[tid] = va[tid];
    if (tid == 0) { scal[0] = -3.4e38f; scal[1] = 0.0f; }
    __syncthreads();

    if (tid < 256) {
        // ========= GEMM warps (0-7): m32 x n64, single fp16 term =========
        const int gm = wid & 3, gn = wid >> 2;
        const uint32_t aBase = (uint32_t)(32 * gm + (lane & 15)) * WSTR
                             + (uint32_t)((lane >> 4) & 1) * 16u;
        const uint32_t aHi0 = sb + OFF_WHI + aBase;
        const uint32_t aHi1 = aHi0 + 16u * WSTR;
        const int ll = lane & 15;
        const uint32_t bBase = (uint32_t)(64 * gn + (ll & 7)) * WSTR
                             + (uint32_t)((ll >> 3) & 1) * 16u;
        const int g = lane >> 2, tc = lane & 3;
        const float v00 = vash[32 * gm + g],      v01 = vash[32 * gm + 8 + g];
        const float v10 = vash[32 * gm + 16 + g], v11 = vash[32 * gm + 24 + g];

        for (int tile = 0; tile < NTILES; tile++) {
            const int p = tile & 1;
            BAR_SYNC(1 + p, 512);                  // H(tile) ready
            const uint32_t bH = sb + OFF_H + (uint32_t)p * 34816u + bBase;

            float acc[2][8][4];
            #pragma unroll
            for (int mi = 0; mi < 2; mi++)
                #pragma unroll
                for (int j = 0; j < 8; j++)
                    #pragma unroll
                    for (int q = 0; q < 4; q++) acc[mi][j][q] = 0.0f;

            #pragma unroll 1
            for (int kk = 0; kk < 8; kk++) {
                const uint32_t ko = (uint32_t)kk * 32u;
                uint32_t a0[4], a1[4];
                ldsm_x4(a0, aHi0 + ko); ldsm_x4(a1, aHi1 + ko);
                #pragma unroll
                for (int jh = 0; jh < 2; jh++) {
                    uint32_t bh[4][2];
                    #pragma unroll
                    for (int j4 = 0; j4 < 4; j4++) {
                        const uint32_t bo = (uint32_t)(jh * 4 + j4) * (8u * WSTR) + ko;
                        ldsm_x2(bh[j4][0], bh[j4][1], bH + bo);
                    }
                    #pragma unroll
                    for (int j4 = 0; j4 < 4; j4++) {
                        const int j = jh * 4 + j4;
                        mma16816(acc[0][j], a0, bh[j4][0], bh[j4][1]);
                        mma16816(acc[1][j], a1, bh[j4][0], bh[j4][1]);
                    }
                }
            }
            BAR_ARRIVE(3 + p, 512);                // done reading H(tile)

            // paired f16x2 tanh + va weighting -> e partials (32 dw rows)
            float* ep = epart + p * 528 + gm * 132;
            #pragma unroll
            for (int j = 0; j < 8; j++) {
                float2 ta = tanh2(acc[0][j][0], acc[0][j][2]);
                float2 tb = tanh2(acc[1][j][0], acc[1][j][2]);
                float2 tc2 = tanh2(acc[0][j][1], acc[0][j][3]);
                float2 td = tanh2(acc[1][j][1], acc[1][j][3]);
                float p0 = v00 * ta.x + v01 * ta.y + v10 * tb.x + v11 * tb.y;
                float p1 = v00 * tc2.x + v01 * tc2.y + v10 * td.x + v11 * td.y;
                #pragma unroll
                for (int off = 4; off <= 16; off <<= 1) {
                    p0 += __shfl_xor_sync(0xffffffffu, p0, off);
                    p1 += __shfl_xor_sync(0xffffffffu, p1, off);
                }
                if (lane < 4) {
                    ep[64 * gn + 8 * j + 2 * tc]     = p0;
                    ep[64 * gn + 8 * j + 2 * tc + 1] = p1;
                }
            }
            __threadfence_block();
            BAR_ARRIVE(5 + p, 288);                // e partials ready
        }
    } else {
        // ================= builder warps (8-15) =================
        const int bt = tid - 256;
        const int bw = bt >> 5;            // builder warp 0-7
        const int c  = lane;               // channel
        const float* M0 = Msh + c * 33;           // bias folded in
        const float* M1 = Msh + (32 + c) * 33;
        const float* M2 = Msh + (64 + c) * 33;
        // prefetch index decomposition (i = bt, bt+256, bt+512)
        const int s0i = bt / 130,        o0i = bt - s0i * 130;
        const int s1i = (bt + 256) / 130, o1i = (bt + 256) - s1i * 130;
        const int o2i = bt + 122;          // s=3, only bt<8
        float ctxAcc[4] = {0.0f, 0.0f, 0.0f, 0.0f};

        for (int tile = 0; tile < NTILES; tile++) {
            const int p = tile & 1;
            // -- LDG prefetch (off critical path) --
            const int base = tile * NT;
            int pv0 = seqb[s0i * NL + base + o0i];
            int pv1 = seqb[s1i * NL + base + o1i];
            int pv2 = (bt < 8) ? seqb[3 * NL + base + o2i] : 0;

            BBAR();                                // all builders done prev iter
            sseq[s0i * 132 + o0i] = pv0;
            sseq[s1i * 132 + o1i] = pv1;
            if (bt < 8) sseq[3 * 132 + o2i] = pv2;
            BBAR();                                // sseq visible
            if (tile >= 2) BAR_SYNC(3 + p, 512);   // GEMM(tile-2) done with buf p

            // build H(tile) into buf p: fp16, [n][e] rows; warp bw owns 16 n
            {
                char* hb = smem + OFF_H + p * 34816;
                const int nb = bw * 16;
                int u0[4], u1[4];
                #pragma unroll
                for (int s = 0; s < 4; s++) {
                    u0[s] = sseq[s * 132 + nb];
                    u1[s] = sseq[s * 132 + nb + 1];
                }
                #pragma unroll 2
                for (int i = 0; i < 16; i++) {
                    const int n = nb + i;
                    float v[4];
                    #pragma unroll
                    for (int s = 0; s < 4; s++) {
                        int u2 = sseq[s * 132 + n + 2];
                        v[s] = fmaxf(M0[u0[s]] + M1[u1[s]] + M2[u2], 0.0f);
                        u0[s] = u1[s]; u1[s] = u2;
                    }
                    uint32_t pk0, pk1;
                    asm("cvt.rn.f16x2.f32 %0, %1, %2;" : "=r"(pk0) : "f"(v[1]), "f"(v[0]));
                    asm("cvt.rn.f16x2.f32 %0, %1, %2;" : "=r"(pk1) : "f"(v[3]), "f"(v[2]));
                    uint2 pk = make_uint2(pk0, pk1);
                    *(uint2*)(hb + (uint32_t)n * WSTR + (uint32_t)c * 8u) = pk;
                }
            }
            __threadfence_block();
            BAR_ARRIVE(1 + p, 512);                // H(tile) ready

            if (tile >= 1) {
                const int pp = (tile - 1) & 1;
                if (bw == 0) {
                    BAR_SYNC(5 + pp, 288);         // e partials(tile-1) ready
                    const float* ep = epart + pp * 528;
                    float e[4], mloc = -3.4e38f;
                    #pragma unroll
                    for (int j = 0; j < 4; j++) {
                        int n = lane + j * 32;
                        e[j] = ep[n] + ep[132 + n] + ep[264 + n] + ep[396 + n];
                        mloc = fmaxf(mloc, e[j]);
                    }
                    #pragma unroll
                    for (int off = 16; off; off >>= 1)
                        mloc = fmaxf(mloc, __shfl_xor_sync(0xffffffffu, mloc, off));
                    float m_old = scal[0];
                    float m_new = fmaxf(m_old, mloc);
                    float alpha = __expf(m_old - m_new);
                    float z = 0.0f;
                    #pragma unroll
                    for (int j = 0; j < 4; j++) {
                        float wv = __expf(e[j] - m_new);
                        wsh[lane + j * 32] = wv;
                        z += wv;
                    }
                    #pragma unroll
                    for (int off = 16; off; off >>= 1)
                        z += __shfl_xor_sync(0xffffffffu, z, off);
                    if (lane == 0) {
                        scal[1] = scal[1] * alpha + z;
                        scal[0] = m_new;
                        scal[3] = alpha;
                    }
                }
                BBAR();                            // wsh/alpha published
                // ctx(tile-1): warp bw rows n=bw*16..+16; lane e-quad lane*4..+4
                const float alpha = scal[3];
                const char* hb = smem + OFF_H + pp * 34816;
                float t0 = 0.0f, t1 = 0.0f, t2 = 0.0f, t3 = 0.0f;
                #pragma unroll 4
                for (int i = 0; i < 16; i++) {
                    int n = bw * 16 + i;
                    float wv = wsh[n];
                    uint2 hv = *(const uint2*)(hb + (uint32_t)n * WSTR + (uint32_t)lane * 8u);
                    float2 f0 = __half22float2(*(__half2*)&hv.x);
                    float2 f1 = __half22float2(*(__half2*)&hv.y);
                    t0 += wv * f0.x; t1 += wv * f0.y; t2 += wv * f1.x; t3 += wv * f1.y;
                }
                ctxAcc[0] = ctxAcc[0] * alpha + t0;
                ctxAcc[1] = ctxAcc[1] * alpha + t1;
                ctxAcc[2] = ctxAcc[2] * alpha + t2;
                ctxAcc[3] = ctxAcc[3] * alpha + t3;
            }
        }
        // ---- tail: epilogue for tile 15 (parity 1, H buf 1) ----
        {
            if (bw == 0) {
                BAR_SYNC(5 + 1, 288);
                const float* ep = epart + 528;
                float e[4], mloc = -3.4e38f;
                #pragma unroll
                for (int j = 0; j < 4; j++) {
                    int n = lane + j * 32;
                    e[j] = ep[n] + ep[132 + n] + ep[264 + n] + ep[396 + n];
                    mloc = fmaxf(mloc, e[j]);
                }
                #pragma unroll
                for (int off = 16; off; off >>= 1)
                    mloc = fmaxf(mloc, __shfl_xor_sync(0xffffffffu, mloc, off));
                float m_old = scal[0];
                float m_new = fmaxf(m_old, mloc);
                float alpha = __expf(m_old - m_new);
                float z = 0.0f;
                #pragma unroll
                for (int j = 0; j < 4; j++) {
                    float wv = __expf(e[j] - m_new);
                    wsh[lane + j * 32] = wv;
                    z += wv;
                }
                #pragma unroll
                for (int off = 16; off; off >>= 1)
                    z += __shfl_xor_sync(0xffffffffu, z, off);
                if (lane == 0) {
                    scal[1] = scal[1] * alpha + z;
                    scal[0] = m_new;
                    scal[3] = alpha;
                }
            }
            BBAR();
            const float alpha = scal[3];
            const char* hb = smem + OFF_H + 34816;
            float t0 = 0.0f, t1 = 0.0f, t2 = 0.0f, t3 = 0.0f;
            #pragma unroll 4
            for (int i = 0; i < 16; i++) {
                int n = bw * 16 + i;
                float wv = wsh[n];
                uint2 hv = *(const uint2*)(hb + (uint32_t)n * WSTR + (uint32_t)lane * 8u);
                float2 f0 = __half22float2(*(__half2*)&hv.x);
                float2 f1 = __half22float2(*(__half2*)&hv.y);
                t0 += wv * f0.x; t1 += wv * f0.y; t2 += wv * f1.x; t3 += wv * f1.y;
            }
            ctxAcc[0] = ctxAcc[0] * alpha + t0;
            ctxAcc[1] = ctxAcc[1] * alpha + t1;
            ctxAcc[2] = ctxAcc[2] * alpha + t2;
            ctxAcc[3] = ctxAcc[3] * alpha + t3;
        }
        #pragma unroll
        for (int j = 0; j < 4; j++)
            ctxp[bw * 128 + lane * 4 + j] = ctxAcc[j];
    }

    __syncthreads();
    if (tid < 128) {
        float invz = 1.0f / scal[1];
        float s = 0.0f;
        #pragma unroll
        for (int q = 0; q < 8; q++) s += ctxp[q * 128 + tid];
        out[b * DD + tid] = s * invz;
    }
}

extern "C" void kernel_launch(void* const* d_in, const int* in_sizes, int n_in,
                              void* d_out, int out_size)
{
    const int*   seq   = (const int*)  d_in[0];  // [128, 8194] int32
    const float* emb   = (const float*)d_in[1];  // [26, 5]
    const float* convw = (const float*)d_in[2];  // [32, 5, 3]
    const float* convb = (const float*)d_in[3];  // [32]
    const float* Wa    = (const float*)d_in[4];  // [128, 128]
    const float* va    = (const float*)d_in[5];  // [128]
    float*       out   = (float*)d_out;          // [128, 128]

    cudaFuncSetAttribute(dingo_kernel,
                         cudaFuncAttributeMaxDynamicSharedMemorySize, SMEM_BYTES);
    dingo_kernel<<<NB, TPB, SMEM_BYTES>>>(seq, emb, convw, convb, Wa, va, out);
}